// round 16
// baseline (speedup 1.0000x reference)
#include <cuda_runtime.h>
#include <math_constants.h>

// Problem constants
#define BB 256
#define CC 8
#define MM 16
#define NN 4096
#define CM 128       // CC*MM
#define LEN_R 64
#define LEN_D 64
#define NBLK 8       // tiles along N per b (NN / 512)
#define NTILES (BB * NBLK)   // 2048
#define TPB 256
#define NSM 152
#define PERSIST (NSM * 8)    // 1216 persistent CTAs (8/SM)

// Per-(b, n-tile) partial argmax scratch + per-b ticket + work queue.
// All zero-initialized at load; every counter is reset in-kernel so the
// kernel is deterministic across graph replays.
__device__ float g_pmax[BB][NBLK];
__device__ int   g_pidx[BB][NBLK];
__device__ int   g_ticket[BB];
__device__ int   g_next;   // tile queue head
__device__ int   g_done;   // CTA retirement ticket

// Persistent fused kernel with dynamic tile queue:
//  - tile = (b, blk): 512 columns of outputs[b,:]; thread handles 2 n (float2)
//  - outputs[b,n] = sum_k x[b,k,n] * W[k]
//  - warp-shuffle partial argmax (first occurrence) -> scratch
//  - last tile per b (ticket) reduces partials, writes tail
//  - last CTA to retire resets queue counters (graph-replay safe).
// __launch_bounds__(256, 8) pins 8 blocks/SM (R12/R13: regs>32 -> DRAM 75%).
// tail layout (after outputs): d[B], r[B], d[B] (pytree leaves of (outputs, d, (r,d)))
__global__ __launch_bounds__(TPB, 8) void fused_kernel(
    const float* __restrict__ x, const float* __restrict__ W,
    const float* __restrict__ r_target, const float* __restrict__ d_target,
    float* __restrict__ out, float* __restrict__ tail)
{
    __shared__ float w[CM];
    __shared__ int   s_tile;
    __shared__ float sv[8];
    __shared__ int   si[8];
    __shared__ int   s_last;

    int t = threadIdx.x;
    int warp = t >> 5, lane = t & 31;
    if (t < CM) w[t] = W[t];

    for (;;) {
        if (t == 0) s_tile = atomicAdd(&g_next, 1);
        __syncthreads();                       // also covers w[] on first iter
        int tile = s_tile;
        if (tile >= NTILES) break;

        int b   = tile >> 3;                   // tile / NBLK
        int blk = tile & 7;                    // tile % NBLK
        int n2  = blk * (512 / 2) + t;         // float2 lane within row
        const float2* xb = reinterpret_cast<const float2*>(x)
                         + (size_t)b * CM * (NN / 2);

        float2 acc = make_float2(0.f, 0.f);
        #pragma unroll 16
        for (int k = 0; k < CM; k++) {
            float2 v = xb[(size_t)k * (NN / 2) + n2];
            float wk = w[k];
            acc.x += v.x * wk;
            acc.y += v.y * wk;
        }
        reinterpret_cast<float2*>(out + (size_t)b * NN)[n2] = acc;

        // Thread-local argmax over 2 lanes (strict > keeps first occurrence).
        int nbase = n2 * 2;
        float best = acc.x; int bidx = nbase;
        if (acc.y > best) { best = acc.y; bidx = nbase + 1; }

        // Warp shuffle reduction; lower lane holds lower index.
        #pragma unroll
        for (int off = 16; off > 0; off >>= 1) {
            float ov = __shfl_down_sync(0xffffffffu, best, off);
            int   oi = __shfl_down_sync(0xffffffffu, bidx, off);
            if (ov > best || (ov == best && oi < bidx)) { best = ov; bidx = oi; }
        }

        if (lane == 0) { sv[warp] = best; si[warp] = bidx; }
        __syncthreads();

        if (warp == 0) {
            float fb = (lane < 8) ? sv[lane] : -CUDART_INF_F;
            int   fi = (lane < 8) ? si[lane] : NN;   // sentinel index
            #pragma unroll
            for (int off = 4; off > 0; off >>= 1) {
                float ov = __shfl_down_sync(0xffffffffu, fb, off);
                int   oi = __shfl_down_sync(0xffffffffu, fi, off);
                if (ov > fb || (ov == fb && oi < fi)) { fb = ov; fi = oi; }
            }
            if (lane == 0) {
                g_pmax[b][blk] = fb;
                g_pidx[b][blk] = fi;
                __threadfence();
                int prev = atomicAdd(&g_ticket[b], 1);
                s_last = (prev == NBLK - 1);
            }
        }
        __syncthreads();

        if (s_last && t == 0) {
            // Winner re-reads all partials; volatile forces L2-visible loads
            // (L1 is per-SM and non-coherent for plain global loads).
            volatile float* pm = &g_pmax[b][0];
            volatile int*   pi = &g_pidx[b][0];
            float fb = pm[0];
            int   fi = pi[0];
            #pragma unroll
            for (int j = 1; j < NBLK; j++) {
                float v = pm[j]; int i = pi[j];
                if (v > fb || (v == fb && i < fi)) { fb = v; fi = i; }
            }
            int ri = fi / LEN_R;
            int di = fi - (fi / LEN_R) * LEN_D;
            // .astype(index.dtype) truncates toward zero; replicate via int cast.
            float rv = (float)(long long)(r_target[ri]);
            float dv = (float)(long long)(d_target[di]);
            tail[b]          = dv;  // leaf 2: d
            tail[BB + b]     = rv;  // leaf 3: r
            tail[2 * BB + b] = dv;  // leaf 4: d
            g_ticket[b] = 0;        // reset for next replay
        }
        __syncthreads();            // protect s_tile/s_last reuse next iter
    }

    // Queue reset: last CTA to retire zeroes the counters. Every CTA's final
    // (over-limit) pop happens-before its g_done increment, so after the last
    // increment no pops remain in flight.
    if (t == 0) {
        __threadfence();
        int prev = atomicAdd(&g_done, 1);
        if (prev == PERSIST - 1) {
            atomicExch(&g_next, 0);
            atomicExch(&g_done, 0);
        }
    }
}

extern "C" void kernel_launch(void* const* d_in, const int* in_sizes, int n_in,
                              void* d_out, int out_size)
{
    const float* x  = (const float*)d_in[0];  // [B, C, M, N]
    const float* W  = (const float*)d_in[1];  // [1, C, M, 1] -> 128 floats
    const float* rt = (const float*)d_in[2];  // [64]
    const float* dt = (const float*)d_in[3];  // [64]
    float* out = (float*)d_out;

    fused_kernel<<<PERSIST, TPB>>>(x, W, rt, dt, out, out + (size_t)BB * NN);
}

// round 17
// speedup vs baseline: 1.0289x; 1.0289x over previous
#include <cuda_runtime.h>
#include <math_constants.h>

// Problem constants
#define BB 256
#define CC 8
#define MM 16
#define NN 4096
#define CM 128       // CC*MM
#define LEN_R 64
#define LEN_D 64
#define TPB 64       // small blocks: 4096 total -> 0.2% cross-SM imbalance
#define NBLK 16      // blocks along N per b (NN / (TPB*4))

// Per-(b, n-block) partial argmax scratch + per-b ticket (device globals).
__device__ float g_pmax[BB][NBLK];
__device__ int   g_pidx[BB][NBLK];
__device__ int   g_ticket[BB];

// Fused kernel (64-thread blocks):
//  - outputs[b,n] = sum_k x[b,k,n] * W[k]  (k = c*M+m, 128 terms)
//  - simple float4 mainloop (proven optimal; 32 regs enforced)
//  - warp-shuffle partial argmax (first occurrence) -> scratch
//  - last block per b (ticket) reduces 16 partials, writes tail, resets ticket.
// Why 64-thread blocks: R15's 1024x256t grid left 112 SMs with 7 CTAs and 40
// with 6 (4% critical-path imbalance). 4096x64t gives 27-vs-26 (0.2%).
// __launch_bounds__(64, 32) pins regs<=32 (R12/R13: regs>32 -> DRAM 75%).
// tail layout (after outputs): d[B], r[B], d[B] (pytree leaves of (outputs, d, (r,d)))
__global__ __launch_bounds__(TPB, 32) void fused_kernel(
    const float* __restrict__ x, const float* __restrict__ W,
    const float* __restrict__ r_target, const float* __restrict__ d_target,
    float* __restrict__ out, float* __restrict__ tail)
{
    __shared__ float w[CM];
    int t = threadIdx.x;
    w[t]       = W[t];
    w[t + 64]  = W[t + 64];
    __syncthreads();

    int b  = blockIdx.y;
    int n4 = blockIdx.x * TPB + t;                 // float4 lane index in N/4
    const float4* xb = reinterpret_cast<const float4*>(x) + (size_t)b * CM * (NN / 4);

    float4 acc = make_float4(0.f, 0.f, 0.f, 0.f);
    #pragma unroll 16
    for (int k = 0; k < CM; k++) {
        float4 v = xb[(size_t)k * (NN / 4) + n4];
        float wk = w[k];
        acc.x += v.x * wk;
        acc.y += v.y * wk;
        acc.z += v.z * wk;
        acc.w += v.w * wk;
    }
    reinterpret_cast<float4*>(out + (size_t)b * NN)[n4] = acc;

    // Thread-local argmax over 4 lanes (strict > keeps first occurrence).
    int nbase = n4 * 4;
    float best = acc.x; int bidx = nbase;
    if (acc.y > best) { best = acc.y; bidx = nbase + 1; }
    if (acc.z > best) { best = acc.z; bidx = nbase + 2; }
    if (acc.w > best) { best = acc.w; bidx = nbase + 3; }

    // Warp reduction via shuffles; lower lane holds lower index, so strict >
    // with (==, oi < bidx) keeps first occurrence.
    #pragma unroll
    for (int off = 16; off > 0; off >>= 1) {
        float ov = __shfl_down_sync(0xffffffffu, best, off);
        int   oi = __shfl_down_sync(0xffffffffu, bidx, off);
        if (ov > best || (ov == best && oi < bidx)) { best = ov; bidx = oi; }
    }

    // 2 warp leaders -> smem, one barrier, thread 0 publishes.
    __shared__ float sv[2];
    __shared__ int   si[2];
    int warp = t >> 5, lane = t & 31;
    if (lane == 0) { sv[warp] = best; si[warp] = bidx; }
    __syncthreads();

    if (t == 0) {
        float fb = sv[0]; int fi = si[0];
        if (sv[1] > fb || (sv[1] == fb && si[1] < fi)) { fb = sv[1]; fi = si[1]; }

        g_pmax[b][blockIdx.x] = fb;
        g_pidx[b][blockIdx.x] = fi;
        __threadfence();
        int prev = atomicAdd(&g_ticket[b], 1);

        if (prev == NBLK - 1) {
            // Winner re-reads all partials; volatile forces L2-visible loads
            // (L1 is per-SM and non-coherent for plain global loads).
            volatile float* pm = &g_pmax[b][0];
            volatile int*   pi = &g_pidx[b][0];
            float wb = pm[0];
            int   wi = pi[0];
            #pragma unroll
            for (int j = 1; j < NBLK; j++) {
                float v = pm[j]; int i = pi[j];
                if (v > wb || (v == wb && i < wi)) { wb = v; wi = i; }
            }
            int ri = wi / LEN_R;
            int di = wi - (wi / LEN_R) * LEN_D;
            // .astype(index.dtype) truncates toward zero; replicate via int cast.
            float rv = (float)(long long)(r_target[ri]);
            float dv = (float)(long long)(d_target[di]);
            tail[b]          = dv;  // leaf 2: d
            tail[BB + b]     = rv;  // leaf 3: r
            tail[2 * BB + b] = dv;  // leaf 4: d
            g_ticket[b] = 0;        // reset for next graph replay (deterministic)
        }
    }
}

extern "C" void kernel_launch(void* const* d_in, const int* in_sizes, int n_in,
                              void* d_out, int out_size)
{
    const float* x  = (const float*)d_in[0];  // [B, C, M, N]
    const float* W  = (const float*)d_in[1];  // [1, C, M, 1] -> 128 floats
    const float* rt = (const float*)d_in[2];  // [64]
    const float* dt = (const float*)d_in[3];  // [64]
    float* out = (float*)d_out;

    dim3 grid(NN / (TPB * 4), BB);            // 16 x 256 = 4096 blocks
    fused_kernel<<<grid, TPB>>>(x, W, rt, dt, out, out + (size_t)BB * NN);
}